// round 11
// baseline (speedup 1.0000x reference)
#include <cuda_runtime.h>
#include <cstdint>

#define N_NODES 100000
#define E_MAX   3200000
#define F_IN    495
#define FH      16

// ---- scratch (no device allocations allowed) ----
static __device__ int    d_cnt [N_NODES];
static __device__ float  d_dinv[N_NODES];
static __device__ float4 d_g   [N_NODES * 4];   // raw h (16 floats per node)
static __device__ float4 d_agg [N_NODES * 4];
static __device__ int2   d_edge[E_MAX];         // packed (src, dst)
static __device__ int    d_csr [E_MAX];         // src ids grouped by dst
static __device__ int    d_rs  [N_NODES + 1];   // CSR row starts
static __device__ int    d_cur [N_NODES];       // fill cursors
static __device__ int    d_part[512];           // block sums for scan
static __device__ float  d_p   [N_NODES];
static __device__ float  d_q   [N_NODES];
static __device__ int    d_is64;

// ---------------------------------------------------------------- cp.async helpers
__device__ __forceinline__ void cp_async4(unsigned int smem_addr, const void* gptr, int src_bytes) {
    asm volatile("cp.async.ca.shared.global [%0], [%1], 4, %2;"
                 :: "r"(smem_addr), "l"(gptr), "r"(src_bytes));
}
__device__ __forceinline__ void cp_commit() {
    asm volatile("cp.async.commit_group;");
}
template <int N>
__device__ __forceinline__ void cp_wait() {
    asm volatile("cp.async.wait_group %0;" :: "n"(N));
}

// ---------------------------------------------------------------- packed f32x2 helpers (Blackwell)
__device__ __forceinline__ void fma2(unsigned long long& d, unsigned long long a, unsigned long long b) {
    asm("fma.rn.f32x2 %0, %1, %2, %0;" : "+l"(d) : "l"(a), "l"(b));
}
__device__ __forceinline__ void add2(unsigned long long& d, unsigned long long a) {
    asm("add.rn.f32x2 %0, %0, %1;" : "+l"(d) : "l"(a));
}
__device__ __forceinline__ unsigned long long pack2(float v) {
    unsigned long long r;
    asm("mov.b64 %0, {%1, %1};" : "=l"(r) : "f"(v));
    return r;
}

// ---------------------------------------------------------------- launch 0: zero counts + dtype sniff
__global__ void k_init(const int* __restrict__ w, int n) {
    int v = blockIdx.x * blockDim.x + threadIdx.x;
    if (v < n) d_cnt[v] = 0;
    if (blockIdx.x == 0) {
        int any = 0;
        for (int i = threadIdx.x; i < 1024; i += blockDim.x)
            if (w[2 * i + 1] != 0) any = 1;
        any = __syncthreads_or(any);
        if (threadIdx.x == 0) d_is64 = any ? 0 : 1;
    }
}

// ---------------------------------------------------------------- launch 1: decode -> packed edges + degree count
__global__ void k_conv(const void* __restrict__ ei, int e, int n) {
    int i = blockIdx.x * blockDim.x + threadIdx.x;
    if (i >= e) return;
    int s, d;
    if (d_is64) {
        const long long* p = (const long long*)ei;
        s = (int)p[i];
        d = (int)p[e + i];
    } else {
        const int* p = (const int*)ei;
        s = p[i];
        d = p[e + i];
    }
    if ((unsigned)s >= (unsigned)n) s = 0;
    if ((unsigned)d >= (unsigned)n) d = 0;
    d_edge[i] = make_int2(s, d);
    atomicAdd(&d_cnt[d], 1);
}

// ---------------------------------------------------------------- launch 2: 256-chunk sums
__global__ void k_scan1(int n) {
    __shared__ int sh[256];
    int t = threadIdx.x;
    int v = blockIdx.x * 256 + t;
    sh[t] = (v < n) ? d_cnt[v] : 0;
    __syncthreads();
    for (int st = 128; st > 0; st >>= 1) {
        if (t < st) sh[t] += sh[t + st];
        __syncthreads();
    }
    if (t == 0) d_part[blockIdx.x] = sh[0];
}

// ---------------------------------------------------------------- launch 3 (PROFILED): GEMM1, h = x @ W1 (raw)
// K-tile 32, W slice double-buffered too: smem 40KB -> 4-5 blocks/SM.
// Packed fma.rn.f32x2 halves FMA issue slots.
#define GM_THREADS 256
#define GM_ROWS    128
#define GM_TILEK   32
#define GM_NT      16           // 16 * 32 = 512 >= 495
#define GM_XPITCH  36
#define GM_XBUF    (GM_ROWS * GM_XPITCH)   // 4608 floats
#define GM_WBUF    (GM_TILEK * FH)         // 512 floats
#define GM_SMEM_FLOATS (2 * GM_XBUF + 2 * GM_WBUF)   // 10240 floats = 40KB

__global__ void __launch_bounds__(GM_THREADS, 4) k_gemm1(const float* __restrict__ x,
                                                         const float* __restrict__ W1, int n) {
    extern __shared__ float sm[];
    float* xb[2] = { sm, sm + GM_XBUF };
    float* wb[2] = { sm + 2 * GM_XBUF, sm + 2 * GM_XBUF + GM_WBUF };

    int tid  = threadIdx.x;
    int lane = tid & 31;
    int warp = tid >> 5;
    int row0 = blockIdx.x * GM_ROWS;
    int rloc = (warp & 3) * 32 + lane;      // 0..127
    int row  = row0 + rloc;
    int half = warp >> 2;                   // K-half: warps 0-3 -> 0, warps 4-7 -> 1
    bool owner = (half == 0);

    // staging map for x: col = tid&31, row groups of 8
    int scol = tid & 31;
    int srg  = tid >> 5;                    // 0..7

    unsigned int xb_s[2], wb_s[2];
    xb_s[0] = (unsigned int)__cvta_generic_to_shared(xb[0]);
    xb_s[1] = (unsigned int)__cvta_generic_to_shared(xb[1]);
    wb_s[0] = (unsigned int)__cvta_generic_to_shared(wb[0]);
    wb_s[1] = (unsigned int)__cvta_generic_to_shared(wb[1]);

    unsigned long long acc2[8];
#pragma unroll
    for (int j = 0; j < 8; j++) acc2[j] = 0ull;

    // ---- stage tile 0 ----
    {
        int gk = scol;
        bool kok = (gk < F_IN);
#pragma unroll
        for (int p = 0; p < 16; p++) {
            int r  = srg + 8 * p;
            int gr = row0 + r;
            int ok = (gr < n && kok) ? 4 : 0;
            const float* src = x + ((long long)(ok ? gr : 0)) * F_IN + (ok ? gk : 0);
            cp_async4(xb_s[0] + (unsigned int)(r * GM_XPITCH + scol) * 4u, src, ok);
        }
#pragma unroll
        for (int p = 0; p < 2; p++) {
            int idx = tid + p * 256;
            int ok  = (idx < F_IN * FH) ? 4 : 0;
            cp_async4(wb_s[0] + (unsigned int)idx * 4u, W1 + (ok ? idx : 0), ok);
        }
        cp_commit();
    }

#pragma unroll
    for (int t = 0; t < GM_NT; t++) {
        int cur = t & 1;
        if (t + 1 < GM_NT) {
            int nxt = (t + 1) & 1;
            int k0  = (t + 1) * GM_TILEK;
            int gk  = k0 + scol;
            bool kok = (gk < F_IN);
#pragma unroll
            for (int p = 0; p < 16; p++) {
                int r  = srg + 8 * p;
                int gr = row0 + r;
                int ok = (gr < n && kok) ? 4 : 0;
                const float* src = x + ((long long)(ok ? gr : 0)) * F_IN + (ok ? gk : 0);
                cp_async4(xb_s[nxt] + (unsigned int)(r * GM_XPITCH + scol) * 4u, src, ok);
            }
#pragma unroll
            for (int p = 0; p < 2; p++) {
                int idx  = tid + p * 256;
                int gidx = k0 * FH + idx;
                int ok   = (gidx < F_IN * FH) ? 4 : 0;
                cp_async4(wb_s[nxt] + (unsigned int)idx * 4u, W1 + (ok ? gidx : 0), ok);
            }
            cp_commit();
            cp_wait<1>();
        } else {
            cp_wait<0>();
        }
        __syncthreads();

        // compute: this warp's K-half (16 k values)
        const float4* xr = (const float4*)(xb[cur] + rloc * GM_XPITCH + half * 16);
        const float*  wB = wb[cur] + half * 16 * FH;
#pragma unroll
        for (int kq = 0; kq < 4; kq++) {
            float4 xv = xr[kq];
#pragma unroll
            for (int i = 0; i < 4; i++) {
                float xi = (i == 0) ? xv.x : (i == 1) ? xv.y : (i == 2) ? xv.z : xv.w;
                unsigned long long xx = pack2(xi);
                const ulonglong2* w2 = (const ulonglong2*)(wB + (kq * 4 + i) * FH);
                ulonglong2 wA = w2[0];
                ulonglong2 wBv = w2[1];
                ulonglong2 wC = w2[2];
                ulonglong2 wD = w2[3];
                fma2(acc2[0], xx, wA.x);
                fma2(acc2[1], xx, wA.y);
                fma2(acc2[2], xx, wBv.x);
                fma2(acc2[3], xx, wBv.y);
                fma2(acc2[4], xx, wC.x);
                fma2(acc2[5], xx, wC.y);
                fma2(acc2[6], xx, wD.x);
                fma2(acc2[7], xx, wD.y);
            }
        }
        __syncthreads();
    }

    // combine K-half partials via smem (xb[0] reused; pitch 36 floats = 18 u64, 8B aligned)
    unsigned long long* red = (unsigned long long*)xb[0];
    if (!owner) {
#pragma unroll
        for (int j = 0; j < 8; j++) red[rloc * 18 + j] = acc2[j];
    }
    __syncthreads();
    if (owner && row < n) {
#pragma unroll
        for (int j = 0; j < 8; j++) add2(acc2[j], red[rloc * 18 + j]);
        float4* gp = &d_g[row * 4];
#pragma unroll
        for (int qd = 0; qd < 4; qd++) {
            float2 lo = *(float2*)&acc2[2 * qd];
            float2 hi = *(float2*)&acc2[2 * qd + 1];
            gp[qd] = make_float4(lo.x, lo.y, hi.x, hi.y);
        }
    }
}

// ---------------------------------------------------------------- launch 4: row starts + cursors + dinv
__global__ void k_scan3(int n, int nb) {
    __shared__ int sh[256];
    __shared__ int soff;
    int t = threadIdx.x;
    int part = 0;
    for (int i = t; i < blockIdx.x; i += 256) part += d_part[i];
    sh[t] = part;
    __syncthreads();
    for (int st = 128; st > 0; st >>= 1) {
        if (t < st) sh[t] += sh[t + st];
        __syncthreads();
    }
    if (t == 0) soff = sh[0];
    __syncthreads();

    int v = blockIdx.x * 256 + t;
    int c = (v < n) ? d_cnt[v] : 0;
    sh[t] = c;
    __syncthreads();
    for (int off = 1; off < 256; off <<= 1) {
        int xv = (t >= off) ? sh[t - off] : 0;
        __syncthreads();
        sh[t] += xv;
        __syncthreads();
    }
    if (v < n) {
        int excl = soff + sh[t] - c;
        d_rs[v]  = excl;
        d_cur[v] = excl;
        d_dinv[v] = rsqrtf(1.0f + (float)c);   // +1 self loop
        if (v == n - 1) d_rs[n] = excl + c;
    }
}

// ---------------------------------------------------------------- launch 5: CSR fill
__global__ void k_fill(int e) {
    int i = blockIdx.x * blockDim.x + threadIdx.x;
    if (i >= e) return;
    int2 ed = d_edge[i];
    int pos = atomicAdd(&d_cur[ed.y], 1);
    d_csr[pos] = ed.x;
}

// ---------------------------------------------------------------- gather: agg[v] = h[v]*dinv[v] + sum_e h[src]*dinv[src]
__global__ void __launch_bounds__(256) k_gather(int n) {
    int wid  = (blockIdx.x * blockDim.x + threadIdx.x) >> 5;
    int lane = threadIdx.x & 31;
    if (wid >= n) return;
    int v    = wid;
    int base = d_rs[v];
    int dend = d_rs[v + 1];
    int grp  = lane >> 4;
    int fl   = lane & 15;
    const float* gf = (const float*)d_g;

    float acc = 0.0f;
    int j = base + grp;
    for (; j + 6 < dend; j += 8) {
        int s0 = d_csr[j];
        int s1 = d_csr[j + 2];
        int s2 = d_csr[j + 4];
        int s3 = d_csr[j + 6];
        float w0 = d_dinv[s0], w1 = d_dinv[s1], w2 = d_dinv[s2], w3 = d_dinv[s3];
        float g0 = gf[s0 * 16 + fl], g1 = gf[s1 * 16 + fl];
        float g2 = gf[s2 * 16 + fl], g3 = gf[s3 * 16 + fl];
        acc = fmaf(g0, w0, acc);
        acc = fmaf(g1, w1, acc);
        acc = fmaf(g2, w2, acc);
        acc = fmaf(g3, w3, acc);
    }
    for (; j < dend; j += 2) {
        int s0 = d_csr[j];
        acc = fmaf(gf[s0 * 16 + fl], d_dinv[s0], acc);
    }
    acc += __shfl_down_sync(0xffffffffu, acc, 16);
    if (lane < 16) {
        float* af = (float*)d_agg;
        af[v * 16 + fl] = fmaf(gf[v * 16 + fl], d_dinv[v], acc);
    }
}

// ---------------------------------------------------------------- layer1 finalize + layer2 GEMM -> d_g (raw h2)
__global__ void __launch_bounds__(256) k_mid(const float* __restrict__ W2,
                                             const float* __restrict__ b1, int n) {
    __shared__ float w2s[FH * FH];
    __shared__ float b1s[FH];
    int tid = threadIdx.x;
    if (tid < FH * FH) w2s[tid] = W2[tid];
    if (tid < FH) b1s[tid] = b1[tid];
    __syncthreads();

    int v = blockIdx.x * blockDim.x + tid;
    if (v >= n) return;
    float di = d_dinv[v];
    const float4* ap = &d_agg[v * 4];
    float z[FH];
#pragma unroll
    for (int qd = 0; qd < 4; qd++) {
        float4 a = ap[qd];
        z[4 * qd + 0] = fmaxf(fmaf(di, a.x, b1s[4 * qd + 0]), 0.0f);
        z[4 * qd + 1] = fmaxf(fmaf(di, a.y, b1s[4 * qd + 1]), 0.0f);
        z[4 * qd + 2] = fmaxf(fmaf(di, a.z, b1s[4 * qd + 2]), 0.0f);
        z[4 * qd + 3] = fmaxf(fmaf(di, a.w, b1s[4 * qd + 3]), 0.0f);
    }
    float h[FH];
#pragma unroll
    for (int j = 0; j < FH; j++) h[j] = 0.0f;
#pragma unroll
    for (int k = 0; k < FH; k++) {
        float zk = z[k];
#pragma unroll
        for (int j = 0; j < FH; j++) h[j] = fmaf(zk, w2s[k * FH + j], h[j]);
    }
    float4* gp = &d_g[v * 4];
#pragma unroll
    for (int qd = 0; qd < 4; qd++)
        gp[qd] = make_float4(h[4 * qd], h[4 * qd + 1], h[4 * qd + 2], h[4 * qd + 3]);
}

// ---------------------------------------------------------------- layer2 finalize + separable FC
__global__ void __launch_bounds__(256) k_fin2(const float* __restrict__ b2,
                                              const float* __restrict__ Wfc, int n) {
    __shared__ float wfs[2 * FH];
    __shared__ float b2s[FH];
    int tid = threadIdx.x;
    if (tid < 2 * FH) wfs[tid] = Wfc[tid];
    if (tid < FH) b2s[tid] = b2[tid];
    __syncthreads();

    int v = blockIdx.x * blockDim.x + tid;
    if (v >= n) return;
    float di = d_dinv[v];
    const float4* ap = &d_agg[v * 4];
    float p = 0.0f, q = 0.0f;
#pragma unroll
    for (int qd = 0; qd < 4; qd++) {
        float4 a = ap[qd];
        float zz[4];
        zz[0] = fmaxf(fmaf(di, a.x, b2s[4 * qd + 0]), 0.0f);
        zz[1] = fmaxf(fmaf(di, a.y, b2s[4 * qd + 1]), 0.0f);
        zz[2] = fmaxf(fmaf(di, a.z, b2s[4 * qd + 2]), 0.0f);
        zz[3] = fmaxf(fmaf(di, a.w, b2s[4 * qd + 3]), 0.0f);
#pragma unroll
        for (int u = 0; u < 4; u++) {
            p = fmaf(zz[u], wfs[4 * qd + u], p);
            q = fmaf(zz[u], wfs[FH + 4 * qd + u], q);
        }
    }
    d_p[v] = p;
    d_q[v] = q;
}

// ---------------------------------------------------------------- out[e] = p[src] + q[dst] + bfc
__global__ void k_edge(const float* __restrict__ bfc, float* __restrict__ out, int e) {
    int i = blockIdx.x * blockDim.x + threadIdx.x;
    if (i >= e) return;
    float b = __ldg(bfc);
    int2 ed = d_edge[i];
    out[i] = d_p[ed.x] + d_q[ed.y] + b;
}

// ----------------------------------------------------------------
extern "C" void kernel_launch(void* const* d_in, const int* in_sizes, int n_in,
                              void* d_out, int out_size) {
    const float* x    = (const float*)d_in[0];
    const void*  ei   = d_in[1];
    const float* W1   = (const float*)d_in[2];
    const float* b1   = (const float*)d_in[3];
    const float* W2   = (const float*)d_in[4];
    const float* b2   = (const float*)d_in[5];
    const float* Wfc  = (const float*)d_in[6];
    const float* bfc  = (const float*)d_in[7];
    float*       out  = (float*)d_out;

    int n = in_sizes[0] / F_IN;      // 100000
    int e = in_sizes[1] / 2;         // 3200000

    static const int smem_bytes = GM_SMEM_FLOATS * (int)sizeof(float);
    cudaFuncSetAttribute(k_gemm1, cudaFuncAttributeMaxDynamicSharedMemorySize, smem_bytes);

    int nb_n  = (n + 255) / 256;                 // 391
    int nb_e  = (e + 255) / 256;
    int nb_gm = (n + GM_ROWS - 1) / GM_ROWS;
    int nb_gw = (n * 32 + 255) / 256;            // warp per node

    k_init <<<nb_n, 256>>>((const int*)ei, n);               // 0
    k_conv <<<nb_e, 256>>>(ei, e, n);                        // 1
    k_scan1<<<nb_n, 256>>>(n);                               // 2
    k_gemm1<<<nb_gm, GM_THREADS, smem_bytes>>>(x, W1, n);    // 3  <- profiled slot
    k_scan3<<<nb_n, 256>>>(n, nb_n);                         // 4
    k_fill <<<nb_e, 256>>>(e);                               // 5
    k_gather<<<nb_gw, 256>>>(n);                             // 6
    k_mid  <<<nb_n, 256>>>(W2, b1, n);                       // 7
    k_gather<<<nb_gw, 256>>>(n);                             // 8
    k_fin2 <<<nb_n, 256>>>(b2, Wfc, n);                      // 9
    k_edge <<<nb_e, 256>>>(bfc, out, e);                     // 10
}

// round 12
// speedup vs baseline: 1.1636x; 1.1636x over previous
#include <cuda_runtime.h>
#include <cstdint>

#define N_NODES 100000
#define E_MAX   3200000
#define F_IN    495
#define FH      16

// ---- scratch (no device allocations allowed) ----
static __device__ int    d_cnt [N_NODES];
static __device__ float  d_dinv[N_NODES];
static __device__ float4 d_g   [N_NODES * 4];   // raw h (16 floats per node)
static __device__ float4 d_agg [N_NODES * 4];
static __device__ int2   d_edge[E_MAX];         // packed (src, dst)
static __device__ int    d_csr [E_MAX];         // src ids grouped by dst
static __device__ int    d_rs  [N_NODES + 1];   // CSR row starts
static __device__ int    d_cur [N_NODES];       // fill cursors
static __device__ int    d_part[512];           // block sums for scan
static __device__ float  d_p   [N_NODES];
static __device__ float  d_q   [N_NODES];
static __device__ int    d_is64;

// ---------------------------------------------------------------- cp.async helpers
__device__ __forceinline__ void cp_async4(unsigned int smem_addr, const void* gptr, int src_bytes) {
    asm volatile("cp.async.ca.shared.global [%0], [%1], 4, %2;"
                 :: "r"(smem_addr), "l"(gptr), "r"(src_bytes));
}
__device__ __forceinline__ void cp_commit() {
    asm volatile("cp.async.commit_group;");
}
template <int N>
__device__ __forceinline__ void cp_wait() {
    asm volatile("cp.async.wait_group %0;" :: "n"(N));
}

// ---------------------------------------------------------------- launch 0: zero counts + dtype sniff
__global__ void k_init(const int* __restrict__ w, int n) {
    int v = blockIdx.x * blockDim.x + threadIdx.x;
    if (v < n) d_cnt[v] = 0;
    if (blockIdx.x == 0) {
        int any = 0;
        for (int i = threadIdx.x; i < 1024; i += blockDim.x)
            if (w[2 * i + 1] != 0) any = 1;
        any = __syncthreads_or(any);
        if (threadIdx.x == 0) d_is64 = any ? 0 : 1;
    }
}

// ---------------------------------------------------------------- launch 1: decode -> packed edges + degree count
__global__ void k_conv(const void* __restrict__ ei, int e, int n) {
    int i = blockIdx.x * blockDim.x + threadIdx.x;
    if (i >= e) return;
    int s, d;
    if (d_is64) {
        const long long* p = (const long long*)ei;
        s = (int)p[i];
        d = (int)p[e + i];
    } else {
        const int* p = (const int*)ei;
        s = p[i];
        d = p[e + i];
    }
    if ((unsigned)s >= (unsigned)n) s = 0;
    if ((unsigned)d >= (unsigned)n) d = 0;
    d_edge[i] = make_int2(s, d);
    atomicAdd(&d_cnt[d], 1);
}

// ---------------------------------------------------------------- launch 2: 256-chunk sums
__global__ void k_scan1(int n) {
    __shared__ int sh[256];
    int t = threadIdx.x;
    int v = blockIdx.x * 256 + t;
    sh[t] = (v < n) ? d_cnt[v] : 0;
    __syncthreads();
    for (int st = 128; st > 0; st >>= 1) {
        if (t < st) sh[t] += sh[t + st];
        __syncthreads();
    }
    if (t == 0) d_part[blockIdx.x] = sh[0];
}

// ---------------------------------------------------------------- launch 3 (PROFILED): GEMM1, h = x @ W1 (raw)
// R10 structure (TILEK=64, full W resident, plain fmaf) with GM_ROWS=64 and a
// 4-way K-split: smem 67.6KB -> 3 blocks/SM -> 6 warps/SMSP (was 4).
#define GM_THREADS 256
#define GM_ROWS    64
#define GM_TILEK   64
#define GM_NT      8            // 8 * 64 = 512 >= 495
#define GM_XPITCH  68
#define GM_XBUF    (GM_ROWS * GM_XPITCH)   // 4352 floats
#define GM_KPAD    512
#define GM_SMEM_FLOATS (GM_KPAD * FH + 2 * GM_XBUF)   // 16896 floats = 67.6KB

__global__ void __launch_bounds__(GM_THREADS, 3) k_gemm1(const float* __restrict__ x,
                                                         const float* __restrict__ W1, int n) {
    extern __shared__ float sm[];
    float* Ws = sm;                         // [512][16] zero-padded
    float* xb[2] = { sm + GM_KPAD * FH, sm + GM_KPAD * FH + GM_XBUF };

    int tid  = threadIdx.x;
    int lane = tid & 31;
    int warp = tid >> 5;
    int row0 = blockIdx.x * GM_ROWS;
    int rloc  = (warp & 1) * 32 + lane;     // 0..63
    int row   = row0 + rloc;
    int quart = warp >> 1;                  // K-quarter 0..3 (128 k values each)
    bool owner = (quart == 0);

    for (int i = tid; i < GM_KPAD * FH; i += GM_THREADS)
        Ws[i] = (i < F_IN * FH) ? W1[i] : 0.0f;

    // staging map: col = tid&63, 4-row groups
    int scol = tid & 63;
    int srg  = tid >> 6;                    // 0..3

    unsigned int xb_s[2];
    xb_s[0] = (unsigned int)__cvta_generic_to_shared(xb[0]);
    xb_s[1] = (unsigned int)__cvta_generic_to_shared(xb[1]);

    float acc[FH];
#pragma unroll
    for (int j = 0; j < FH; j++) acc[j] = 0.0f;

    // ---- stage tile 0 ----
    {
        int gk = scol;
        bool kok = (gk < F_IN);
#pragma unroll
        for (int p = 0; p < 16; p++) {
            int r  = srg + 4 * p;
            int gr = row0 + r;
            int ok = (gr < n && kok) ? 4 : 0;
            const float* src = x + ((long long)(ok ? gr : 0)) * F_IN + (ok ? gk : 0);
            cp_async4(xb_s[0] + (unsigned int)(r * GM_XPITCH + scol) * 4u, src, ok);
        }
        cp_commit();
    }

#pragma unroll
    for (int t = 0; t < GM_NT; t++) {
        int cur = t & 1;
        if (t + 1 < GM_NT) {
            int gk = (t + 1) * GM_TILEK + scol;
            bool kok = (gk < F_IN);
            int nxt = (t + 1) & 1;
#pragma unroll
            for (int p = 0; p < 16; p++) {
                int r  = srg + 4 * p;
                int gr = row0 + r;
                int ok = (gr < n && kok) ? 4 : 0;
                const float* src = x + ((long long)(ok ? gr : 0)) * F_IN + (ok ? gk : 0);
                cp_async4(xb_s[nxt] + (unsigned int)(r * GM_XPITCH + scol) * 4u, src, ok);
            }
            cp_commit();
            cp_wait<1>();
        } else {
            cp_wait<0>();
        }
        __syncthreads();

        // compute tile t: this warp's K-quarter (16 k values = 4 float4)
        const float4* xr = (const float4*)(xb[cur] + rloc * GM_XPITCH);
        int kq0 = quart * 4;
#pragma unroll
        for (int kq = 0; kq < 4; kq++) {
            float4 xv = xr[kq0 + kq];
            const float4* w4 = (const float4*)(Ws + (t * GM_TILEK + (kq0 + kq) * 4) * FH);
#pragma unroll
            for (int i = 0; i < 4; i++) {
                float xi = (i == 0) ? xv.x : (i == 1) ? xv.y : (i == 2) ? xv.z : xv.w;
                float4 b0 = w4[i * 4 + 0];
                float4 b1 = w4[i * 4 + 1];
                float4 b2 = w4[i * 4 + 2];
                float4 b3 = w4[i * 4 + 3];
                acc[0]  = fmaf(xi, b0.x, acc[0]);
                acc[1]  = fmaf(xi, b0.y, acc[1]);
                acc[2]  = fmaf(xi, b0.z, acc[2]);
                acc[3]  = fmaf(xi, b0.w, acc[3]);
                acc[4]  = fmaf(xi, b1.x, acc[4]);
                acc[5]  = fmaf(xi, b1.y, acc[5]);
                acc[6]  = fmaf(xi, b1.z, acc[6]);
                acc[7]  = fmaf(xi, b1.w, acc[7]);
                acc[8]  = fmaf(xi, b2.x, acc[8]);
                acc[9]  = fmaf(xi, b2.y, acc[9]);
                acc[10] = fmaf(xi, b2.z, acc[10]);
                acc[11] = fmaf(xi, b2.w, acc[11]);
                acc[12] = fmaf(xi, b3.x, acc[12]);
                acc[13] = fmaf(xi, b3.y, acc[13]);
                acc[14] = fmaf(xi, b3.z, acc[14]);
                acc[15] = fmaf(xi, b3.w, acc[15]);
            }
        }
        __syncthreads();
    }

    // combine the 4 K-quarter partials: quarters 1-3 dump to xb[0], quarter 0 adds.
    // slot (q-1): 64 rows x 16 floats (64B-aligned float4 blocks).
    float* red = xb[0];
    if (!owner) {
        float4* r4 = (float4*)(red + ((quart - 1) * GM_ROWS + rloc) * 16);
#pragma unroll
        for (int qd = 0; qd < 4; qd++)
            r4[qd] = make_float4(acc[4 * qd], acc[4 * qd + 1], acc[4 * qd + 2], acc[4 * qd + 3]);
    }
    __syncthreads();
    if (owner && row < n) {
#pragma unroll
        for (int q = 1; q < 4; q++) {
            const float* rr = red + ((q - 1) * GM_ROWS + rloc) * 16;
#pragma unroll
            for (int j = 0; j < FH; j++) acc[j] += rr[j];
        }
        float4* gp = &d_g[row * 4];
#pragma unroll
        for (int qd = 0; qd < 4; qd++)
            gp[qd] = make_float4(acc[4 * qd], acc[4 * qd + 1],
                                 acc[4 * qd + 2], acc[4 * qd + 3]);
    }
}

// ---------------------------------------------------------------- launch 4: row starts + cursors + dinv
__global__ void k_scan3(int n, int nb) {
    __shared__ int sh[256];
    __shared__ int soff;
    int t = threadIdx.x;
    int part = 0;
    for (int i = t; i < blockIdx.x; i += 256) part += d_part[i];
    sh[t] = part;
    __syncthreads();
    for (int st = 128; st > 0; st >>= 1) {
        if (t < st) sh[t] += sh[t + st];
        __syncthreads();
    }
    if (t == 0) soff = sh[0];
    __syncthreads();

    int v = blockIdx.x * 256 + t;
    int c = (v < n) ? d_cnt[v] : 0;
    sh[t] = c;
    __syncthreads();
    for (int off = 1; off < 256; off <<= 1) {
        int xv = (t >= off) ? sh[t - off] : 0;
        __syncthreads();
        sh[t] += xv;
        __syncthreads();
    }
    if (v < n) {
        int excl = soff + sh[t] - c;
        d_rs[v]  = excl;
        d_cur[v] = excl;
        d_dinv[v] = rsqrtf(1.0f + (float)c);   // +1 self loop
        if (v == n - 1) d_rs[n] = excl + c;
    }
}

// ---------------------------------------------------------------- launch 5: CSR fill
__global__ void k_fill(int e) {
    int i = blockIdx.x * blockDim.x + threadIdx.x;
    if (i >= e) return;
    int2 ed = d_edge[i];
    int pos = atomicAdd(&d_cur[ed.y], 1);
    d_csr[pos] = ed.x;
}

// ---------------------------------------------------------------- gather: agg[v] = h[v]*dinv[v] + sum_e h[src]*dinv[src]
__global__ void __launch_bounds__(256) k_gather(int n) {
    int wid  = (blockIdx.x * blockDim.x + threadIdx.x) >> 5;
    int lane = threadIdx.x & 31;
    if (wid >= n) return;
    int v    = wid;
    int base = d_rs[v];
    int dend = d_rs[v + 1];
    int grp  = lane >> 4;
    int fl   = lane & 15;
    const float* gf = (const float*)d_g;

    float acc = 0.0f;
    int j = base + grp;
    for (; j + 6 < dend; j += 8) {
        int s0 = d_csr[j];
        int s1 = d_csr[j + 2];
        int s2 = d_csr[j + 4];
        int s3 = d_csr[j + 6];
        float w0 = d_dinv[s0], w1 = d_dinv[s1], w2 = d_dinv[s2], w3 = d_dinv[s3];
        float g0 = gf[s0 * 16 + fl], g1 = gf[s1 * 16 + fl];
        float g2 = gf[s2 * 16 + fl], g3 = gf[s3 * 16 + fl];
        acc = fmaf(g0, w0, acc);
        acc = fmaf(g1, w1, acc);
        acc = fmaf(g2, w2, acc);
        acc = fmaf(g3, w3, acc);
    }
    for (; j < dend; j += 2) {
        int s0 = d_csr[j];
        acc = fmaf(gf[s0 * 16 + fl], d_dinv[s0], acc);
    }
    acc += __shfl_down_sync(0xffffffffu, acc, 16);
    if (lane < 16) {
        float* af = (float*)d_agg;
        af[v * 16 + fl] = fmaf(gf[v * 16 + fl], d_dinv[v], acc);
    }
}

// ---------------------------------------------------------------- layer1 finalize + layer2 GEMM -> d_g (raw h2)
__global__ void __launch_bounds__(256) k_mid(const float* __restrict__ W2,
                                             const float* __restrict__ b1, int n) {
    __shared__ float w2s[FH * FH];
    __shared__ float b1s[FH];
    int tid = threadIdx.x;
    if (tid < FH * FH) w2s[tid] = W2[tid];
    if (tid < FH) b1s[tid] = b1[tid];
    __syncthreads();

    int v = blockIdx.x * blockDim.x + tid;
    if (v >= n) return;
    float di = d_dinv[v];
    const float4* ap = &d_agg[v * 4];
    float z[FH];
#pragma unroll
    for (int qd = 0; qd < 4; qd++) {
        float4 a = ap[qd];
        z[4 * qd + 0] = fmaxf(fmaf(di, a.x, b1s[4 * qd + 0]), 0.0f);
        z[4 * qd + 1] = fmaxf(fmaf(di, a.y, b1s[4 * qd + 1]), 0.0f);
        z[4 * qd + 2] = fmaxf(fmaf(di, a.z, b1s[4 * qd + 2]), 0.0f);
        z[4 * qd + 3] = fmaxf(fmaf(di, a.w, b1s[4 * qd + 3]), 0.0f);
    }
    float h[FH];
#pragma unroll
    for (int j = 0; j < FH; j++) h[j] = 0.0f;
#pragma unroll
    for (int k = 0; k < FH; k++) {
        float zk = z[k];
#pragma unroll
        for (int j = 0; j < FH; j++) h[j] = fmaf(zk, w2s[k * FH + j], h[j]);
    }
    float4* gp = &d_g[v * 4];
#pragma unroll
    for (int qd = 0; qd < 4; qd++)
        gp[qd] = make_float4(h[4 * qd], h[4 * qd + 1], h[4 * qd + 2], h[4 * qd + 3]);
}

// ---------------------------------------------------------------- layer2 finalize + separable FC
__global__ void __launch_bounds__(256) k_fin2(const float* __restrict__ b2,
                                              const float* __restrict__ Wfc, int n) {
    __shared__ float wfs[2 * FH];
    __shared__ float b2s[FH];
    int tid = threadIdx.x;
    if (tid < 2 * FH) wfs[tid] = Wfc[tid];
    if (tid < FH) b2s[tid] = b2[tid];
    __syncthreads();

    int v = blockIdx.x * blockDim.x + tid;
    if (v >= n) return;
    float di = d_dinv[v];
    const float4* ap = &d_agg[v * 4];
    float p = 0.0f, q = 0.0f;
#pragma unroll
    for (int qd = 0; qd < 4; qd++) {
        float4 a = ap[qd];
        float zz[4];
        zz[0] = fmaxf(fmaf(di, a.x, b2s[4 * qd + 0]), 0.0f);
        zz[1] = fmaxf(fmaf(di, a.y, b2s[4 * qd + 1]), 0.0f);
        zz[2] = fmaxf(fmaf(di, a.z, b2s[4 * qd + 2]), 0.0f);
        zz[3] = fmaxf(fmaf(di, a.w, b2s[4 * qd + 3]), 0.0f);
#pragma unroll
        for (int u = 0; u < 4; u++) {
            p = fmaf(zz[u], wfs[4 * qd + u], p);
            q = fmaf(zz[u], wfs[FH + 4 * qd + u], q);
        }
    }
    d_p[v] = p;
    d_q[v] = q;
}

// ---------------------------------------------------------------- out[e] = p[src] + q[dst] + bfc
__global__ void k_edge(const float* __restrict__ bfc, float* __restrict__ out, int e) {
    int i = blockIdx.x * blockDim.x + threadIdx.x;
    if (i >= e) return;
    float b = __ldg(bfc);
    int2 ed = d_edge[i];
    out[i] = d_p[ed.x] + d_q[ed.y] + b;
}

// ----------------------------------------------------------------
extern "C" void kernel_launch(void* const* d_in, const int* in_sizes, int n_in,
                              void* d_out, int out_size) {
    const float* x    = (const float*)d_in[0];
    const void*  ei   = d_in[1];
    const float* W1   = (const float*)d_in[2];
    const float* b1   = (const float*)d_in[3];
    const float* W2   = (const float*)d_in[4];
    const float* b2   = (const float*)d_in[5];
    const float* Wfc  = (const float*)d_in[6];
    const float* bfc  = (const float*)d_in[7];
    float*       out  = (float*)d_out;

    int n = in_sizes[0] / F_IN;      // 100000
    int e = in_sizes[1] / 2;         // 3200000

    static const int smem_bytes = GM_SMEM_FLOATS * (int)sizeof(float);
    cudaFuncSetAttribute(k_gemm1, cudaFuncAttributeMaxDynamicSharedMemorySize, smem_bytes);

    int nb_n  = (n + 255) / 256;                 // 391
    int nb_e  = (e + 255) / 256;
    int nb_gm = (n + GM_ROWS - 1) / GM_ROWS;     // 1563
    int nb_gw = (n * 32 + 255) / 256;            // warp per node

    k_init <<<nb_n, 256>>>((const int*)ei, n);               // 0
    k_conv <<<nb_e, 256>>>(ei, e, n);                        // 1
    k_scan1<<<nb_n, 256>>>(n);                               // 2
    k_gemm1<<<nb_gm, GM_THREADS, smem_bytes>>>(x, W1, n);    // 3  <- profiled slot
    k_scan3<<<nb_n, 256>>>(n, nb_n);                         // 4
    k_fill <<<nb_e, 256>>>(e);                               // 5
    k_gather<<<nb_gw, 256>>>(n);                             // 6
    k_mid  <<<nb_n, 256>>>(W2, b1, n);                       // 7
    k_gather<<<nb_gw, 256>>>(n);                             // 8
    k_fin2 <<<nb_n, 256>>>(b2, Wfc, n);                      // 9
    k_edge <<<nb_e, 256>>>(bfc, out, e);                     // 10
}